// round 13
// baseline (speedup 1.0000x reference)
#include <cuda_runtime.h>
#include <cstddef>

// ===========================================================================
// mh_attention — exact restructure honoring the literal [16,128]->[4,16,32]
// reshape: slot kk of head h -> (neighbor nb = h*4+(kk>>2), ch-block cb = kk&3)
//
//   q[n]        = Wq x[n] + bq                                   [128]
//   t[n,h,cb]   = q_h . bk[cb*32:+32]
//   r[n,h,cb,:] = Wk[cb*32:+32,:]^T q_h                          [16][128]
//   logit[h,kk] = (nf[n,nb].r[h,cb] + t[h,cb]) / sqrt(128)
//   att         = softmax over the 16 kk slots per head
//   s[h,cb,:]   = sum_a att[h,a*4+cb] * nf[n,h*4+a]
//   out[h*32+d] = sum_cb Wv[cb*32+d,:].s[h,cb] + sum_cb asum[h,cb]*bv[cb*32+d]
// All fp32 via fma.rn.f32x2 -> ~1e-6 of reference.
// ===========================================================================

#define CC    128
#define KK    16
#define HH    4
#define NPAD  132      // padded row: 33x16B (odd) -> conflict-free LDS.128
#define NMAX  100000
#define TP    8        // points per tile (kernel B)
#define GRID_B 148
#define NTHR  256

__device__ float g_q[(size_t)NMAX * CC];   // 51.2 MB scratch

// ---- exact packed-fp32 helpers ----
__device__ __forceinline__ unsigned long long ffma2(unsigned long long a,
                                                    unsigned long long b,
                                                    unsigned long long c) {
    unsigned long long d;
    asm("fma.rn.f32x2 %0, %1, %2, %3;" : "=l"(d) : "l"(a), "l"(b), "l"(c));
    return d;
}
__device__ __forceinline__ float f2sum(unsigned long long a) {
    float lo, hi;
    asm("mov.b64 {%0,%1}, %2;" : "=f"(lo), "=f"(hi) : "l"(a));
    return lo + hi;
}
__device__ __forceinline__ unsigned long long f2pack(float lo, float hi) {
    unsigned long long r;
    asm("mov.b64 %0, {%1,%2};" : "=l"(r) : "f"(lo), "f"(hi));
    return r;
}

// ============================ Kernel A: q projection ========================
#define A_PTS 16
static const size_t SMEM_A_FLOATS = (size_t)CC*NPAD + CC + (size_t)A_PTS*CC;

__global__ __launch_bounds__(NTHR)
void qproj_kernel(const float* __restrict__ x_feat,
                  const float* __restrict__ Wq, const float* __restrict__ bq,
                  int N)
{
    extern __shared__ float sm[];
    float* Wq_s = sm;                 // [128][132]
    float* bq_s = Wq_s + CC*NPAD;     // [128]
    float* xs   = bq_s + CC;          // [16][128]

    const int tid = threadIdx.x;
    for (int idx = tid; idx < CC*CC; idx += NTHR)
        Wq_s[(idx >> 7)*NPAD + (idx & 127)] = Wq[idx];
    if (tid < CC) bq_s[tid] = bq[tid];

    const int base = blockIdx.x * A_PTS;
    #pragma unroll
    for (int i = 0; i < 2; ++i) {                 // stage 16x128 x
        int v = tid + NTHR*i;
        int p = v >> 5, d4 = v & 31;
        int n = base + p; if (n >= N) n = N - 1;
        *(float4*)(xs + p*CC + d4*4) =
            *(const float4*)(x_feat + (size_t)n*CC + d4*4);
    }
    __syncthreads();

    const int c  = tid & 127;
    const int p0 = (tid >> 7) * 8;

    unsigned long long acc[8];
    float b = bq_s[c];
    #pragma unroll
    for (int p = 0; p < 8; ++p) acc[p] = f2pack(b, 0.f);

    const ulonglong2* w2 = (const ulonglong2*)(Wq_s + c*NPAD);
    #pragma unroll 8
    for (int d4 = 0; d4 < 32; ++d4) {
        ulonglong2 w = w2[d4];
        #pragma unroll
        for (int p = 0; p < 8; ++p) {
            ulonglong2 xv = *(const ulonglong2*)(xs + (p0 + p)*CC + d4*4);
            acc[p] = ffma2(w.x, xv.x, acc[p]);
            acc[p] = ffma2(w.y, xv.y, acc[p]);
        }
    }
    #pragma unroll
    for (int p = 0; p < 8; ++p) {
        int n = base + p0 + p;
        if (n < N) g_q[(size_t)n*CC + c] = f2sum(acc[p]);
    }
}

// ======================= Kernel B: persistent fused =========================
static const size_t SMEM_B_FLOATS =
      (size_t)CC*NPAD        // WvR[e][d][cb] (+4 pad)       16896
    + (size_t)TP*KK*NPAD     // nf_s                          16896
    + (size_t)TP*KK*NPAD     // rs (r, then reused as sR)     16896
    + (size_t)TP*CC          // qs                             1024
    + (size_t)TP*KK          // ts                              128
    + (size_t)TP*HH*KK       // att_s (logits -> att)           512
    + (size_t)TP*HH*HH       // asum_s                          128
    + CC + CC;               // bv_s, bk_s                      256

__global__ __launch_bounds__(NTHR, 1)
void attn_kernel(const float* __restrict__ nfeat, const float* __restrict__ xyz,
                 const float* __restrict__ Wk, const float* __restrict__ Wv,
                 const float* __restrict__ bk, const float* __restrict__ bv,
                 float* __restrict__ out, int N, int ntiles)
{
    extern __shared__ float sm[];
    float* WvR    = sm;
    float* nf_s   = WvR    + CC*NPAD;
    float* rs     = nf_s   + (size_t)TP*KK*NPAD;   // r, then sR[p][h][e][cb]
    float* qs     = rs     + (size_t)TP*KK*NPAD;
    float* ts     = qs     + TP*CC;
    float* att_s  = ts     + TP*KK;
    float* asum_s = att_s  + TP*HH*KK;
    float* bv_s   = asum_s + TP*HH*HH;
    float* bk_s   = bv_s   + CC;

    const int tid = threadIdx.x;
    const int e   = tid & 127;
    const int z   = tid >> 7;

    // WvR[e][d][cb] = Wv[(cb*32+d)*128 + e]
    for (int idx = tid; idx < CC*CC; idx += NTHR) {
        int m = idx >> 7, ee = idx & 127;
        WvR[ee*NPAD + (m & 31)*4 + (m >> 5)] = Wv[idx];
    }
    if (tid < CC) { bv_s[tid] = bv[tid]; bk_s[tid] = bk[tid]; }

    // Wk -> registers: thread (e,z) owns Wk[c][e] for c in [z*64, z*64+64)
    unsigned long long wk2[2][16];
    #pragma unroll
    for (int cbl = 0; cbl < 2; ++cbl) {
        int cb = 2*z + cbl;
        #pragma unroll
        for (int d2 = 0; d2 < 16; ++d2) {
            int c = cb*32 + 2*d2;
            wk2[cbl][d2] = f2pack(Wk[(size_t)c*CC + e],
                                  Wk[(size_t)(c + 1)*CC + e]);
        }
    }

    float4 xz[16];
    auto prefetch = [&](int tile_) {
        int b16 = tile_ * (TP * KK);              // global row n*16+j base
        #pragma unroll
        for (int i = 0; i < 16; ++i) {
            int v = tid + NTHR*i;                 // 0..4095 float4 chunks
            int pj = v >> 5, e4 = v & 31;
            long long gj = (long long)b16 + pj;
            if (gj >= (long long)N * KK) gj = (long long)N * KK - 1;
            const float* src = nfeat + (size_t)gj*CC + e4*4;
            unsigned dst = (unsigned)__cvta_generic_to_shared(nf_s + pj*NPAD + e4*4);
            asm volatile("cp.async.cg.shared.global [%0], [%1], 16;"
                         :: "r"(dst), "l"(src) : "memory");
            xz[i] = *(const float4*)(xyz + (size_t)gj*CC + e4*4);
        }
        asm volatile("cp.async.commit_group;" ::: "memory");
    };

    int tile = blockIdx.x;
    if (tile < ntiles) prefetch(tile);
    __syncthreads();   // WvR / bv / bk visible

    for (; tile < ntiles; tile += GRID_B) {
        const int base = tile * TP;

        // ---- merge nf = new_feature (cp.async) + xyz (regs) ----
        asm volatile("cp.async.wait_group 0;" ::: "memory");
        #pragma unroll
        for (int i = 0; i < 16; ++i) {
            int v = tid + NTHR*i;
            int pj = v >> 5, e4 = v & 31;
            float4* d = (float4*)(nf_s + pj*NPAD + e4*4);
            float4 cur = *d;
            cur.x += xz[i].x; cur.y += xz[i].y;
            cur.z += xz[i].z; cur.w += xz[i].w;
            *d = cur;
        }
        // ---- stage q ----
        {
            int p = tid >> 5, d4 = tid & 31;
            int n = base + p; if (n >= N) n = N - 1;
            *(float4*)(qs + p*CC + d4*4) =
                *(const float4*)(g_q + (size_t)n*CC + d4*4);
        }
        __syncthreads();

        // ---- R phase: r[p][h*4+cb][e], thread owns cb in {2z, 2z+1} ----
        #pragma unroll 1
        for (int p = 0; p < TP; ++p) {
            unsigned long long racc[HH][2];
            #pragma unroll
            for (int h = 0; h < HH; ++h) { racc[h][0] = 0ull; racc[h][1] = 0ull; }
            #pragma unroll
            for (int d4 = 0; d4 < 8; ++d4) {
                #pragma unroll
                for (int h = 0; h < HH; ++h) {
                    ulonglong2 qv = *(const ulonglong2*)(qs + p*CC + h*32 + d4*4);
                    racc[h][0] = ffma2(wk2[0][2*d4],     qv.x, racc[h][0]);
                    racc[h][0] = ffma2(wk2[0][2*d4 + 1], qv.y, racc[h][0]);
                    racc[h][1] = ffma2(wk2[1][2*d4],     qv.x, racc[h][1]);
                    racc[h][1] = ffma2(wk2[1][2*d4 + 1], qv.y, racc[h][1]);
                }
            }
            #pragma unroll
            for (int h = 0; h < HH; ++h) {
                rs[(p*KK + h*4 + 2*z    )*NPAD + e] = f2sum(racc[h][0]);
                rs[(p*KK + h*4 + 2*z + 1)*NPAD + e] = f2sum(racc[h][1]);
            }
        }
        // ---- t[p][h*4+cb] = q_h . bk_cb ----
        if (tid < 128) {
            int p = tid >> 4, g = tid & 15, h = g >> 2, cb = g & 3;
            unsigned long long ta = 0ull;
            #pragma unroll
            for (int d4 = 0; d4 < 8; ++d4) {
                ulonglong2 qv = *(const ulonglong2*)(qs + p*CC + h*32 + d4*4);
                ulonglong2 bb = *(const ulonglong2*)(bk_s + cb*32 + d4*4);
                ta = ffma2(qv.x, bb.x, ta);
                ta = ffma2(qv.y, bb.y, ta);
            }
            ts[p*KK + g] = f2sum(ta);
        }
        __syncthreads();

        // ---- L phase: 512 logits, 2 per thread (conflict-free 8-row spread) --
        #pragma unroll
        for (int rep = 0; rep < 2; ++rep) {
            int idx = tid + rep*NTHR;
            int cb = idx & 3, nb = (idx >> 2) & 15, p = idx >> 6;
            int h = nb >> 2, a = nb & 3;
            const float* nfr = nf_s + (p*KK + nb)*NPAD;
            const float* rr  = rs   + (p*KK + h*4 + cb)*NPAD;
            unsigned long long da = 0ull, db = 0ull;
            #pragma unroll 8
            for (int i4 = 0; i4 < 32; ++i4) {
                ulonglong2 nv = *(const ulonglong2*)(nfr + i4*4);
                ulonglong2 rv = *(const ulonglong2*)(rr  + i4*4);
                da = ffma2(nv.x, rv.x, da);
                db = ffma2(nv.y, rv.y, db);
            }
            float lg = (f2sum(da) + f2sum(db) + ts[p*KK + h*4 + cb])
                     * 0.08838834764831845f;     // 1/sqrt(128)
            att_s[(p*HH + h)*KK + a*4 + cb] = lg;
        }
        __syncthreads();

        // ---- softmax over 16 slots per (p,h); also asum[p][h][cb] ----
        {
            int kk = tid & 15, gi = tid >> 4;
            #pragma unroll
            for (int rep = 0; rep < 2; ++rep) {
                int ph = gi + rep*16;                  // p*4+h, 0..31
                float l = att_s[ph*KK + kk];
                float mx = l;
                #pragma unroll
                for (int o = 1; o < 16; o <<= 1)
                    mx = fmaxf(mx, __shfl_xor_sync(0xffffffffu, mx, o));
                float ev = __expf(l - mx);
                float sme = ev;
                #pragma unroll
                for (int o = 1; o < 16; o <<= 1)
                    sme += __shfl_xor_sync(0xffffffffu, sme, o);
                float av = ev / sme;
                att_s[ph*KK + kk] = av;
                float as = av + __shfl_xor_sync(0xffffffffu, av, 4);
                as += __shfl_xor_sync(0xffffffffu, as, 8);
                if (kk < 4) asum_s[ph*4 + kk] = as;    // lane kk==cb
            }
        }
        __syncthreads();

        // ---- S phase: sR[p][h][e][cb] = sum_a att[h,a*4+cb]*nf[h*4+a][e] ----
        #pragma unroll 1
        for (int pl = 0; pl < 4; ++pl) {
            int p = z*4 + pl;
            #pragma unroll
            for (int h = 0; h < HH; ++h) {
                unsigned long long s01 = 0ull, s23 = 0ull;
                const float* ab = att_s + (p*HH + h)*KK;
                #pragma unroll
                for (int a = 0; a < 4; ++a) {
                    float nv = nf_s[(p*KK + h*4 + a)*NPAD + e];
                    unsigned long long nn = f2pack(nv, nv);
                    ulonglong2 at = *(const ulonglong2*)(ab + a*4);
                    s01 = ffma2(at.x, nn, s01);
                    s23 = ffma2(at.y, nn, s23);
                }
                ulonglong2 sv; sv.x = s01; sv.y = s23;
                *(ulonglong2*)(rs + ((p*HH + h)*CC + e)*4) = sv;
            }
        }
        __syncthreads();

        // ---- issue next-tile prefetch (hides under OUT) ----
        {
            int nxt = tile + GRID_B;
            if (nxt < ntiles) prefetch(nxt);
        }

        // ---- OUT phase: out[m=h*32+d] over 4 points per thread-group ----
        {
            int m = e, h = m >> 5, d = m & 31;
            int p0o = z * 4;
            unsigned long long acc[4][2];
            #pragma unroll
            for (int pl = 0; pl < 4; ++pl) { acc[pl][0] = 0ull; acc[pl][1] = 0ull; }
            #pragma unroll 4
            for (int ee = 0; ee < CC; ++ee) {
                ulonglong2 wv = *(const ulonglong2*)(WvR + ee*NPAD + d*4);
                #pragma unroll
                for (int pl = 0; pl < 4; ++pl) {
                    ulonglong2 sv = *(const ulonglong2*)
                        (rs + (((p0o + pl)*HH + h)*CC + ee)*4);
                    acc[pl][0] = ffma2(wv.x, sv.x, acc[pl][0]);
                    acc[pl][1] = ffma2(wv.y, sv.y, acc[pl][1]);
                }
            }
            float bv0 = bv_s[d], bv1 = bv_s[32 + d],
                  bv2 = bv_s[64 + d], bv3 = bv_s[96 + d];
            #pragma unroll
            for (int pl = 0; pl < 4; ++pl) {
                int p = p0o + pl;
                float4 a4 = *(const float4*)(asum_s + (p*HH + h)*4);
                float val = f2sum(acc[pl][0]) + f2sum(acc[pl][1])
                          + a4.x*bv0 + a4.y*bv1 + a4.z*bv2 + a4.w*bv3;
                int n = base + p;
                if (n < N) out[(size_t)n*CC + m] = val;
            }
        }
        __syncthreads();
    }
}

// ================================ launch ====================================
extern "C" void kernel_launch(void* const* d_in, const int* in_sizes, int n_in,
                              void* d_out, int out_size)
{
    // order: x_feat, xyz_enc, new_feature, head, d_k, Wq, bq, Wk, bk, Wv, bv
    const float* x_feat = (const float*)d_in[0];
    const float* xyz    = (const float*)d_in[1];
    const float* nfeat  = (const float*)d_in[2];
    const float* Wq     = (const float*)d_in[5];
    const float* bq     = (const float*)d_in[6];
    const float* Wk     = (const float*)d_in[7];
    const float* bk     = (const float*)d_in[8];
    const float* Wv     = (const float*)d_in[9];
    const float* bv     = (const float*)d_in[10];
    float* out = (float*)d_out;

    int N = in_sizes[0] / CC;
    if (N > NMAX) N = NMAX;

    const int smA = (int)(SMEM_A_FLOATS * sizeof(float));   //  76 KB
    const int smB = (int)(SMEM_B_FLOATS * sizeof(float));   // 206 KB
    cudaFuncSetAttribute(qproj_kernel, cudaFuncAttributeMaxDynamicSharedMemorySize, smA);
    cudaFuncSetAttribute(attn_kernel,  cudaFuncAttributeMaxDynamicSharedMemorySize, smB);

    int ntiles = (N + TP - 1) / TP;
    int gridA  = (N + A_PTS - 1) / A_PTS;
    int gridB  = ntiles < GRID_B ? ntiles : GRID_B;

    qproj_kernel<<<gridA, NTHR, smA>>>(x_feat, Wq, bq, N);
    attn_kernel<<<gridB, NTHR, smB>>>(nfeat, xyz, Wk, Wv, bk, bv, out, N, ntiles);
}